// round 13
// baseline (speedup 1.0000x reference)
#include <cuda_runtime.h>

// FlowLenia single step. SX=SY=256, C=3, K=15, DD=5, DT=0.2, SIGMA=0.65
// Output: newA (256*256*3) followed by newP (256*256*15), float32.
//
// R11: R10 + programmatic dependent launch (PDL) across all 6 kernels to
//      overlap launch/drain gaps. Kernel math unchanged from R10.

#define NPIX 65536
static __device__ float4 g_F4[NPIX];          // 2 planes of float2
static __device__ float4 g_tmp4[4 * NPIX];    // 8 planes of float2
#define G_F   ((float2*)g_F4)
#define G_TMP ((float2*)g_tmp4)
static __device__ float  g_G[15 * NPIX];      // growth(U), [k][x][y]
static __device__ float  g_mu[NPIX * 6];      // [row_c0..2, col_c0..2]

__device__ __forceinline__ float2 cmulf(float2 a, float2 b) {
    return make_float2(a.x * b.x - a.y * b.y, a.x * b.y + a.y * b.x);
}
__device__ __forceinline__ float2 csqr(float2 a) {
    return make_float2(a.x * a.x - a.y * a.y, 2.0f * a.x * a.y);
}
__device__ __forceinline__ float2 cadd(float2 a, float2 b) {
    return make_float2(a.x + b.x, a.y + b.y);
}
__device__ __forceinline__ float2 csub(float2 a, float2 b) {
    return make_float2(a.x - b.x, a.y - b.y);
}
__device__ __forceinline__ int brev5(int l) {
    return ((l & 1) << 4) | ((l & 2) << 2) | (l & 4) | ((l & 8) >> 2) | ((l & 16) >> 4);
}

// 256-pt FFT across a 64-thread group (t = tid&63), v[r] = x[t + 64r].
// Output: thread t, reg q holds X[q + 4*(t>>5) + 8*brev5(t&31)].
// ONE sincospif per thread; other twiddles derived algebraically.
template <bool INV>
__device__ __forceinline__ void group_fft256(float2 v[4], float2* xch, int t) {
    const float SGN = INV ? 1.0f : -1.0f;
    const float RH = 0.70710678118654752f;
    int l = t & 31;
    int w = t >> 5;
    // radix-4 DIF
    float2 e0 = cadd(v[0], v[2]);
    float2 e1 = csub(v[0], v[2]);
    float2 o0 = cadd(v[1], v[3]);
    float2 o1 = csub(v[1], v[3]);
    float2 io1 = make_float2(-SGN * o1.y, SGN * o1.x);
    v[0] = cadd(e0, o0);
    v[2] = csub(e0, o0);
    v[1] = cadd(e1, io1);
    v[3] = csub(e1, io1);
    // middle twiddles W256^{t*q}
    float sn, cs;
    sincospif(SGN * (float)t * (1.0f / 128.0f), &sn, &cs);
    float2 w1 = make_float2(cs, sn);
    float2 w2 = csqr(w1);
    float2 w3 = cmulf(w2, w1);
    v[1] = cmulf(v[1], w1);
    v[2] = cmulf(v[2], w2);
    v[3] = cmulf(v[3], w3);
    // twiddle chain: W256^l -> W64^l -> stage twiddles
    float2 wl = (t & 32) ? cmulf(w1, make_float2(RH, -SGN * RH)) : w1; // W256^l
    float2 w64l = csqr(csqr(wl));                                      // W64^l
    // cross-warp butterfly t <-> t^32 via smem
#pragma unroll
    for (int q = 0; q < 4; q++) xch[q * 66 + t] = v[q];
    __syncthreads();
    {
        int pt = t ^ 32;
#pragma unroll
        for (int q = 0; q < 4; q++) {
            float2 p = xch[q * 66 + pt];
            if (w == 0) v[q] = cadd(v[q], p);
            else        v[q] = cmulf(csub(p, v[q]), w64l);
        }
    }
    // stage twiddles
    float2 w32l = csqr(w64l);                                          // W32^l
    float2 tw0 = (l & 16) ? make_float2(-w32l.x, -w32l.y) : w32l;      // W32^{l&15}
    float2 u1  = (l & 8) ? make_float2(SGN * tw0.y, -SGN * tw0.x) : tw0; // W32^{l&7}
    float2 tw1 = csqr(u1);                                             // W16^{l&7}
    float2 u2  = (l & 4) ? make_float2(SGN * tw1.y, -SGN * tw1.x) : tw1; // W16^{l&3}
    float2 tw2 = csqr(u2);                                             // W8^{l&3}
    float2 tws[3] = {tw0, tw1, tw2};
    // stages 0..2 (h = 16, 8, 4)
#pragma unroll
    for (int s5 = 0; s5 < 3; s5++) {
        int h = 16 >> s5;
        bool up = (l & h) != 0;
        float2 tw = tws[s5];
#pragma unroll
        for (int q = 0; q < 4; q++) {
            float2 p;
            p.x = __shfl_xor_sync(0xffffffffu, v[q].x, h);
            p.y = __shfl_xor_sync(0xffffffffu, v[q].y, h);
            if (up) v[q] = cmulf(csub(p, v[q]), tw);
            else    v[q] = cadd(v[q], p);
        }
    }
    // stage 3 (h=2): twiddle = (l&1) ? +SGN*i : 1
    {
        bool up = (l & 2) != 0;
        bool r1 = (l & 1) != 0;
#pragma unroll
        for (int q = 0; q < 4; q++) {
            float2 p;
            p.x = __shfl_xor_sync(0xffffffffu, v[q].x, 2);
            p.y = __shfl_xor_sync(0xffffffffu, v[q].y, 2);
            float2 d = csub(p, v[q]);
            float2 dr = r1 ? make_float2(-SGN * d.y, SGN * d.x) : d;
            v[q] = up ? dr : cadd(v[q], p);
        }
    }
    // stage 4 (h=1): twiddle = 1
    {
        bool up = (l & 1) != 0;
#pragma unroll
        for (int q = 0; q < 4; q++) {
            float2 p;
            p.x = __shfl_xor_sync(0xffffffffu, v[q].x, 1);
            p.y = __shfl_xor_sync(0xffffffffu, v[q].y, 1);
            v[q] = up ? csub(p, v[q]) : cadd(v[q], p);
        }
    }
}

__device__ __forceinline__ int out_k0(int t) {
    return ((t >> 5) << 2) + 8 * brev5(t & 31);
}

// ---- Pass 1: forward row FFT (along y). plane0 = A0+i*A1, plane1 = A2 ----
__global__ __launch_bounds__(256) void k_fwd_rows(const float* __restrict__ A) {
    __shared__ float2 xch[4][4 * 66];
    int tid = threadIdx.x;
    int g = tid >> 6, t = tid & 63;
    int gid = blockIdx.x * 4 + g;   // 0..511
    int plane = gid >> 8;
    int x = gid & 255;
    float2 v[4];
#pragma unroll
    for (int r = 0; r < 4; r++) {
        int gi = (x * 256 + t + 64 * r) * 3;
        v[r] = (plane == 0) ? make_float2(A[gi], A[gi + 1])
                            : make_float2(A[gi + 2], 0.0f);
    }
    group_fft256<false>(v, xch[g], t);
    int k0 = out_k0(t);
    float4* out = (float4*)(G_F + plane * NPIX + x * 256 + k0);
    out[0] = make_float4(v[0].x, v[0].y, v[1].x, v[1].y);
    out[1] = make_float4(v[2].x, v[2].y, v[3].x, v[3].y);
}

// ---- Pass 2: forward column FFT (along x), 4 columns per 256-thr block ----
__global__ __launch_bounds__(256) void k_fwd_cols() {
    cudaGridDependencySynchronize();
    __shared__ float2 stage[4 * 292];
    __shared__ float2 xch[4][4 * 66];
    int b = blockIdx.x;             // 2*64
    int plane = b >> 6;
    int y0 = (b & 63) * 4;
    float2* base = G_F + plane * NPIX;
    int tid = threadIdx.x;
    for (int i = tid; i < 512; i += 256) {
        int x = i >> 1, h = i & 1;
        float4 ld = *(const float4*)(base + x * 256 + y0 + 2 * h);
        stage[(2 * h) * 292 + x]     = make_float2(ld.x, ld.y);
        stage[(2 * h + 1) * 292 + x] = make_float2(ld.z, ld.w);
    }
    __syncthreads();
    int g = tid >> 6, t = tid & 63;
    float2 v[4];
#pragma unroll
    for (int r = 0; r < 4; r++) v[r] = stage[g * 292 + t + 64 * r];
    group_fft256<false>(v, xch[g], t);
    int k0 = out_k0(t);
#pragma unroll
    for (int q = 0; q < 4; q++) {
        int k = k0 + q;
        stage[g * 292 + k + (k >> 3)] = v[q];
    }
    __syncthreads();
    for (int i = tid; i < 512; i += 256) {
        int x = i >> 1, h = i & 1;
        float2 s0 = stage[(2 * h) * 292 + x + (x >> 3)];
        float2 s1 = stage[(2 * h + 1) * 292 + x + (x >> 3)];
        *(float4*)(base + x * 256 + y0 + 2 * h) = make_float4(s0.x, s0.y, s1.x, s1.y);
    }
}

// ---- Pass 3: spectral multiply (Hermitian unpack) + inverse row FFT ----
__global__ __launch_bounds__(256) void k_inv_rows(const float* __restrict__ fKr,
                                                  const float* __restrict__ fKi) {
    cudaGridDependencySynchronize();
    __shared__ float2 xch[4][4 * 66];
    int tid = threadIdx.x;
    int g = tid >> 6, t = tid & 63;
    int gid = blockIdx.x * 4 + g;   // 0..2047
    int j = gid >> 8, x = gid & 255;
    int k1 = 2 * j, k2 = 2 * j + 1;
    bool k2v = (j < 7);
    int c1 = k1 % 3, c2 = k2 % 3;
    int xr = (256 - x) & 255;
    float2 v[4];
#pragma unroll
    for (int r = 0; r < 4; r++) {
        int y = t + 64 * r;
        int gi = x * 256 + y;
        int yr = (256 - y) & 255;
        float2 fv = G_F[gi];
        float2 fr = G_F[xr * 256 + yr];
        float2 fa0 = make_float2(0.5f * (fv.x + fr.x), 0.5f * (fv.y - fr.y));
        float2 fa1 = make_float2(0.5f * (fv.y + fr.y), 0.5f * (fr.x - fv.x));
        float2 fa2 = G_F[NPIX + gi];
        float2 fc1 = (c1 == 0) ? fa0 : ((c1 == 1) ? fa1 : fa2);
        float2 H1 = cmulf(make_float2(fKr[gi * 15 + k1], fKi[gi * 15 + k1]), fc1);
        float2 H2 = make_float2(0.f, 0.f);
        if (k2v) {
            float2 fc2 = (c2 == 0) ? fa0 : ((c2 == 1) ? fa1 : fa2);
            H2 = cmulf(make_float2(fKr[gi * 15 + k2], fKi[gi * 15 + k2]), fc2);
        }
        v[r] = make_float2(H1.x - H2.y, H1.y + H2.x);
    }
    group_fft256<true>(v, xch[g], t);
    int k0 = out_k0(t);
    float4* out = (float4*)(G_TMP + j * NPIX + x * 256 + k0);
    out[0] = make_float4(v[0].x, v[0].y, v[1].x, v[1].y);
    out[1] = make_float4(v[2].x, v[2].y, v[3].x, v[3].y);
}

// ---- Pass 4: inverse column FFT + growth -> g_G[k1], g_G[k2] ----
__global__ __launch_bounds__(256) void k_inv_cols(const float* __restrict__ m,
                                                  const float* __restrict__ s) {
    cudaGridDependencySynchronize();
    __shared__ float2 stage[4 * 292];
    __shared__ float2 xch[4][4 * 66];
    int b = blockIdx.x;             // 8*64
    int j = b >> 6;
    int y0 = (b & 63) * 4;
    int k1 = 2 * j, k2 = 2 * j + 1;
    bool k2v = (j < 7);
    float2* base = G_TMP + j * NPIX;
    int tid = threadIdx.x;
    for (int i = tid; i < 512; i += 256) {
        int x = i >> 1, h = i & 1;
        float4 ld = *(const float4*)(base + x * 256 + y0 + 2 * h);
        stage[(2 * h) * 292 + x]     = make_float2(ld.x, ld.y);
        stage[(2 * h + 1) * 292 + x] = make_float2(ld.z, ld.w);
    }
    __syncthreads();
    int g = tid >> 6, t = tid & 63;
    float2 v[4];
#pragma unroll
    for (int r = 0; r < 4; r++) v[r] = stage[g * 292 + t + 64 * r];
    group_fft256<true>(v, xch[g], t);
    float m1 = m[k1], s1 = s[k1];
    float i2s1 = 1.0f / (2.0f * s1 * s1);
    float m2 = k2v ? m[k2] : 0.f, s2 = k2v ? s[k2] : 1.f;
    float i2s2 = 1.0f / (2.0f * s2 * s2);
    int k0 = out_k0(t);
#pragma unroll
    for (int q = 0; q < 4; q++) {
        float u1 = v[q].x * (1.0f / 65536.0f);
        float t1 = u1 - m1;
        float g1 = fmaf(2.0f, __expf(-t1 * t1 * i2s1), -1.0f);
        float u2 = v[q].y * (1.0f / 65536.0f);
        float t2 = u2 - m2;
        float g2 = fmaf(2.0f, __expf(-t2 * t2 * i2s2), -1.0f);
        int k = k0 + q;
        stage[g * 292 + k + (k >> 3)] = make_float2(g1, g2);
    }
    __syncthreads();
    for (int i = tid; i < 512; i += 256) {
        int x = i & 255, pl = i >> 8;
        if (pl == 1 && !k2v) continue;
        float2 s0 = stage[0 * 292 + x + (x >> 3)];
        float2 s1 = stage[1 * 292 + x + (x >> 3)];
        float2 s2 = stage[2 * 292 + x + (x >> 3)];
        float2 s3 = stage[3 * 292 + x + (x >> 3)];
        float4 out = (pl == 0) ? make_float4(s0.x, s1.x, s2.x, s3.x)
                               : make_float4(s0.y, s1.y, s2.y, s3.y);
        int kk = (pl == 0) ? k1 : k2;
        *(float4*)(g_G + kk * NPIX + x * 256 + y0) = out;
    }
}

// ---- Pass 5: fused UcAs (18x18 halo tile) + Sobel + mu ----
__global__ __launch_bounds__(256) void k_ucas_sobel(const float* __restrict__ A,
                                                    const float* __restrict__ P) {
    cudaGridDependencySynchronize();
    const float SIGMA = 0.65f, MAB = 4.35f, DT = 0.2f;
    __shared__ float4 sU[18 * 18];
    int x0 = blockIdx.y * 16;
    int y0 = blockIdx.x * 16;
    int tid = threadIdx.x;
    for (int i = tid; i < 324; i += 256) {
        int ti = i / 18, tj = i - ti * 18;
        int gx = x0 + ti - 1, gy = y0 + tj - 1;
        float4 val = make_float4(0.f, 0.f, 0.f, 0.f);
        if ((unsigned)gx < 256u && (unsigned)gy < 256u) {
            int gi = gx * 256 + gy;
            float u[3] = {0.f, 0.f, 0.f};
#pragma unroll
            for (int k = 0; k < 15; k++) u[k % 3] += g_G[k * NPIX + gi] * P[gi * 15 + k];
            val = make_float4(u[0], u[1], u[2],
                              A[gi * 3 + 0] + A[gi * 3 + 1] + A[gi * 3 + 2]);
        }
        sU[i] = val;
    }
    __syncthreads();
    int li = tid >> 4, lj = tid & 15;
    int x = x0 + li, y = y0 + lj;
    int i = x * 256 + y;
    float4 S[3][3];
#pragma unroll
    for (int du = 0; du < 3; du++)
#pragma unroll
        for (int dv = 0; dv < 3; dv++)
            S[du][dv] = sU[(li + du) * 18 + (lj + dv)];
    float gy[4], gx[4];
    {
        float4 b0 = S[2][0], b1 = S[2][1], b2 = S[2][2];
        float4 t0 = S[0][0], t1 = S[0][1], t2 = S[0][2];
        gy[0] = (b0.x + 2.f * b1.x + b2.x) - (t0.x + 2.f * t1.x + t2.x);
        gy[1] = (b0.y + 2.f * b1.y + b2.y) - (t0.y + 2.f * t1.y + t2.y);
        gy[2] = (b0.z + 2.f * b1.z + b2.z) - (t0.z + 2.f * t1.z + t2.z);
        gy[3] = (b0.w + 2.f * b1.w + b2.w) - (t0.w + 2.f * t1.w + t2.w);
        float4 r0 = S[0][2], r1 = S[1][2], r2 = S[2][2];
        float4 l0 = S[0][0], l1 = S[1][0], l2 = S[2][0];
        gx[0] = (r0.x + 2.f * r1.x + r2.x) - (l0.x + 2.f * l1.x + l2.x);
        gx[1] = (r0.y + 2.f * r1.y + r2.y) - (l0.y + 2.f * l1.y + l2.y);
        gx[2] = (r0.z + 2.f * r1.z + r2.z) - (l0.z + 2.f * l1.z + l2.z);
        gx[3] = (r0.w + 2.f * r1.w + r2.w) - (l0.w + 2.f * l1.w + l2.w);
    }
    float pr = (float)x + 0.5f, pc = (float)y + 0.5f;
#pragma unroll
    for (int c = 0; c < 3; c++) {
        float a = A[i * 3 + c];
        float al = fminf(0.25f * a * a, 1.0f);
        float Fy = gy[c] * (1.0f - al) - gy[3] * al;
        float Fx = gx[c] * (1.0f - al) - gx[3] * al;
        Fy = fminf(fmaxf(Fy, -MAB), MAB);
        Fx = fminf(fmaxf(Fx, -MAB), MAB);
        float mur = fminf(fmaxf(pr + DT * Fy, SIGMA), 256.0f - SIGMA);
        float muc = fminf(fmaxf(pc + DT * Fx, SIGMA), 256.0f - SIGMA);
        g_mu[i * 6 + c]     = mur;
        g_mu[i * 6 + 3 + c] = muc;
    }
}

// ---- Pass 6: reintegration gather (25-source window), softmax-mixed P ----
__global__ __launch_bounds__(256) void k_reint(const float* __restrict__ A,
                                               const float* __restrict__ P,
                                               float* __restrict__ outA,
                                               float* __restrict__ outP) {
    cudaGridDependencySynchronize();
    const float SIGMA = 0.65f;
    const float INV4S2 = 1.0f / (4.0f * 0.65f * 0.65f);
    __shared__ float s_mu[400 * 6];
    __shared__ float s_A[400 * 3];
    __shared__ __align__(16) float s_P[400 * 20];
    int x0 = blockIdx.y * 16;
    int y0 = blockIdx.x * 16;
    int tid = threadIdx.x;
    for (int cidx = tid; cidx < 400; cidx += 256) {
        int ti = cidx / 20, tj = cidx - ti * 20;
        int gx = x0 + ti - 2, gy = y0 + tj - 2;
        bool ok = (unsigned)gx < 256u && (unsigned)gy < 256u;
        int gi = gx * 256 + gy;
#pragma unroll
        for (int f = 0; f < 6; f++) s_mu[cidx * 6 + f] = ok ? g_mu[gi * 6 + f] : -1.0e4f;
#pragma unroll
        for (int c = 0; c < 3; c++) s_A[cidx * 3 + c] = ok ? A[gi * 3 + c] : 0.0f;
#pragma unroll
        for (int k = 0; k < 15; k++) s_P[cidx * 20 + k] = ok ? P[gi * 15 + k] : 0.0f;
        s_P[cidx * 20 + 15] = 0.0f;
    }
    __syncthreads();

    int li = tid >> 4, lj = tid & 15;
    int x = x0 + li, y = y0 + lj;
    float pr = (float)x + 0.5f, pc = (float)y + 0.5f;
    float accA[3] = {0.f, 0.f, 0.f};
    float4 n0 = make_float4(0.f, 0.f, 0.f, 0.f), n1 = n0, n2 = n0, n3 = n0;
    float den = 0.0f;

    for (int di = 0; di < 5; di++) {
#pragma unroll
        for (int dj = 0; dj < 5; dj++) {
            int cell = (li + di) * 20 + (lj + dj);
            const float* mu = &s_mu[cell * 6];
            float ssum = 0.0f;
#pragma unroll
            for (int c = 0; c < 3; c++) {
                float szr = 0.5f + SIGMA - fabsf(pr - mu[c]);
                float szc = 0.5f + SIGMA - fabsf(pc - mu[3 + c]);
                float ar = fminf(fmaxf(szr, 0.0f), 1.0f) *
                           fminf(fmaxf(szc, 0.0f), 1.0f) * INV4S2;
                float nA = s_A[cell * 3 + c] * ar;
                accA[c] += nA;
                ssum += nA;
            }
            // ssum >= 0; ssum == 0 -> e == 0 -> exactly zero contribution
            if (ssum != 0.0f) {
                float e = __expf(ssum) - 1.0f;
                den += e;
                const float4* p4 = (const float4*)(s_P + cell * 20);
                float4 a0 = p4[0], a1 = p4[1], a2 = p4[2], a3 = p4[3];
                n0.x += a0.x * e; n0.y += a0.y * e; n0.z += a0.z * e; n0.w += a0.w * e;
                n1.x += a1.x * e; n1.y += a1.y * e; n1.z += a1.z * e; n1.w += a1.w * e;
                n2.x += a2.x * e; n2.y += a2.y * e; n2.z += a2.z * e; n2.w += a2.w * e;
                n3.x += a3.x * e; n3.y += a3.y * e; n3.z += a3.z * e;
            }
        }
    }
    int gi = x * 256 + y;
#pragma unroll
    for (int c = 0; c < 3; c++) outA[gi * 3 + c] = accA[c];
    float inv = 1.0f / (den + 1e-10f);
    float num[15] = {n0.x, n0.y, n0.z, n0.w, n1.x, n1.y, n1.z, n1.w,
                     n2.x, n2.y, n2.z, n2.w, n3.x, n3.y, n3.z};
#pragma unroll
    for (int k = 0; k < 15; k++) outP[gi * 15 + k] = num[k] * inv;
}

// ---- host: PDL launches ----
template <typename K, typename... Args>
static inline void launch_pdl(K kern, dim3 grid, dim3 block, Args... args) {
    cudaLaunchConfig_t cfg = {};
    cfg.gridDim = grid;
    cfg.blockDim = block;
    cfg.dynamicSmemBytes = 0;
    cfg.stream = 0;
    cudaLaunchAttribute attr[1];
    attr[0].id = cudaLaunchAttributeProgrammaticStreamSerialization;
    attr[0].val.programmaticStreamSerializationAllowed = 1;
    cfg.attrs = attr;
    cfg.numAttrs = 1;
    cudaLaunchKernelEx(&cfg, kern, args...);
}

extern "C" void kernel_launch(void* const* d_in, const int* in_sizes, int n_in,
                              void* d_out, int out_size) {
    const float* A   = (const float*)d_in[0];
    const float* P   = (const float*)d_in[1];
    const float* fKr = (const float*)d_in[2];
    const float* fKi = (const float*)d_in[3];
    const float* m   = (const float*)d_in[4];
    const float* s   = (const float*)d_in[5];
    float* outA = (float*)d_out;
    float* outP = (float*)d_out + 256 * 256 * 3;

    k_fwd_rows<<<128, 256>>>(A);
    launch_pdl(k_fwd_cols, dim3(128), dim3(256));
    launch_pdl(k_inv_rows, dim3(512), dim3(256), fKr, fKi);
    launch_pdl(k_inv_cols, dim3(512), dim3(256), m, s);
    launch_pdl(k_ucas_sobel, dim3(16, 16), dim3(256), A, P);
    launch_pdl(k_reint, dim3(16, 16), dim3(256), A, P, outA, outP);
}

// round 14
// speedup vs baseline: 1.4164x; 1.4164x over previous
#include <cuda_runtime.h>

// FlowLenia single step. SX=SY=256, C=3, K=15, DD=5, DT=0.2, SIGMA=0.65
// Output: newA (256*256*3) followed by newP (256*256*15), float32.
//
// R12: PDL reverted (plain launches, R10 baseline). k_inv_rows restructured:
//      one 512-thread block per x-row, fK row staged coalesced into smem
//      (kills the 60B-stride gather amplification), 8 j-plane groups/block.

#define NPIX 65536
static __device__ float4 g_F4[NPIX];          // 2 planes of float2
static __device__ float4 g_tmp4[4 * NPIX];    // 8 planes of float2
#define G_F   ((float2*)g_F4)
#define G_TMP ((float2*)g_tmp4)
static __device__ float  g_G[15 * NPIX];      // growth(U), [k][x][y]
static __device__ float  g_mu[NPIX * 6];      // [row_c0..2, col_c0..2]

__device__ __forceinline__ float2 cmulf(float2 a, float2 b) {
    return make_float2(a.x * b.x - a.y * b.y, a.x * b.y + a.y * b.x);
}
__device__ __forceinline__ float2 csqr(float2 a) {
    return make_float2(a.x * a.x - a.y * a.y, 2.0f * a.x * a.y);
}
__device__ __forceinline__ float2 cadd(float2 a, float2 b) {
    return make_float2(a.x + b.x, a.y + b.y);
}
__device__ __forceinline__ float2 csub(float2 a, float2 b) {
    return make_float2(a.x - b.x, a.y - b.y);
}
__device__ __forceinline__ int brev5(int l) {
    return ((l & 1) << 4) | ((l & 2) << 2) | (l & 4) | ((l & 8) >> 2) | ((l & 16) >> 4);
}

// 256-pt FFT across a 64-thread group (t = tid&63), v[r] = x[t + 64r].
// Output: thread t, reg q holds X[q + 4*(t>>5) + 8*brev5(t&31)].
// ONE sincospif per thread; other twiddles derived algebraically.
// Contains ONE block-wide __syncthreads (all groups must call unconditionally).
template <bool INV>
__device__ __forceinline__ void group_fft256(float2 v[4], float2* xch, int t) {
    const float SGN = INV ? 1.0f : -1.0f;
    const float RH = 0.70710678118654752f;
    int l = t & 31;
    int w = t >> 5;
    // radix-4 DIF
    float2 e0 = cadd(v[0], v[2]);
    float2 e1 = csub(v[0], v[2]);
    float2 o0 = cadd(v[1], v[3]);
    float2 o1 = csub(v[1], v[3]);
    float2 io1 = make_float2(-SGN * o1.y, SGN * o1.x);
    v[0] = cadd(e0, o0);
    v[2] = csub(e0, o0);
    v[1] = cadd(e1, io1);
    v[3] = csub(e1, io1);
    // middle twiddles W256^{t*q}
    float sn, cs;
    sincospif(SGN * (float)t * (1.0f / 128.0f), &sn, &cs);
    float2 w1 = make_float2(cs, sn);
    float2 w2 = csqr(w1);
    float2 w3 = cmulf(w2, w1);
    v[1] = cmulf(v[1], w1);
    v[2] = cmulf(v[2], w2);
    v[3] = cmulf(v[3], w3);
    // twiddle chain: W256^l -> W64^l -> stage twiddles
    float2 wl = (t & 32) ? cmulf(w1, make_float2(RH, -SGN * RH)) : w1; // W256^l
    float2 w64l = csqr(csqr(wl));                                      // W64^l
    // cross-warp butterfly t <-> t^32 via smem
#pragma unroll
    for (int q = 0; q < 4; q++) xch[q * 66 + t] = v[q];
    __syncthreads();
    {
        int pt = t ^ 32;
#pragma unroll
        for (int q = 0; q < 4; q++) {
            float2 p = xch[q * 66 + pt];
            if (w == 0) v[q] = cadd(v[q], p);
            else        v[q] = cmulf(csub(p, v[q]), w64l);
        }
    }
    // stage twiddles
    float2 w32l = csqr(w64l);                                          // W32^l
    float2 tw0 = (l & 16) ? make_float2(-w32l.x, -w32l.y) : w32l;      // W32^{l&15}
    float2 u1  = (l & 8) ? make_float2(SGN * tw0.y, -SGN * tw0.x) : tw0; // W32^{l&7}
    float2 tw1 = csqr(u1);                                             // W16^{l&7}
    float2 u2  = (l & 4) ? make_float2(SGN * tw1.y, -SGN * tw1.x) : tw1; // W16^{l&3}
    float2 tw2 = csqr(u2);                                             // W8^{l&3}
    float2 tws[3] = {tw0, tw1, tw2};
    // stages 0..2 (h = 16, 8, 4)
#pragma unroll
    for (int s5 = 0; s5 < 3; s5++) {
        int h = 16 >> s5;
        bool up = (l & h) != 0;
        float2 tw = tws[s5];
#pragma unroll
        for (int q = 0; q < 4; q++) {
            float2 p;
            p.x = __shfl_xor_sync(0xffffffffu, v[q].x, h);
            p.y = __shfl_xor_sync(0xffffffffu, v[q].y, h);
            if (up) v[q] = cmulf(csub(p, v[q]), tw);
            else    v[q] = cadd(v[q], p);
        }
    }
    // stage 3 (h=2): twiddle = (l&1) ? +SGN*i : 1
    {
        bool up = (l & 2) != 0;
        bool r1 = (l & 1) != 0;
#pragma unroll
        for (int q = 0; q < 4; q++) {
            float2 p;
            p.x = __shfl_xor_sync(0xffffffffu, v[q].x, 2);
            p.y = __shfl_xor_sync(0xffffffffu, v[q].y, 2);
            float2 d = csub(p, v[q]);
            float2 dr = r1 ? make_float2(-SGN * d.y, SGN * d.x) : d;
            v[q] = up ? dr : cadd(v[q], p);
        }
    }
    // stage 4 (h=1): twiddle = 1
    {
        bool up = (l & 1) != 0;
#pragma unroll
        for (int q = 0; q < 4; q++) {
            float2 p;
            p.x = __shfl_xor_sync(0xffffffffu, v[q].x, 1);
            p.y = __shfl_xor_sync(0xffffffffu, v[q].y, 1);
            v[q] = up ? csub(p, v[q]) : cadd(v[q], p);
        }
    }
}

__device__ __forceinline__ int out_k0(int t) {
    return ((t >> 5) << 2) + 8 * brev5(t & 31);
}

// ---- Pass 1: forward row FFT (along y). plane0 = A0+i*A1, plane1 = A2 ----
__global__ __launch_bounds__(256) void k_fwd_rows(const float* __restrict__ A) {
    __shared__ float2 xch[4][4 * 66];
    int tid = threadIdx.x;
    int g = tid >> 6, t = tid & 63;
    int gid = blockIdx.x * 4 + g;   // 0..511
    int plane = gid >> 8;
    int x = gid & 255;
    float2 v[4];
#pragma unroll
    for (int r = 0; r < 4; r++) {
        int gi = (x * 256 + t + 64 * r) * 3;
        v[r] = (plane == 0) ? make_float2(A[gi], A[gi + 1])
                            : make_float2(A[gi + 2], 0.0f);
    }
    group_fft256<false>(v, xch[g], t);
    int k0 = out_k0(t);
    float4* out = (float4*)(G_F + plane * NPIX + x * 256 + k0);
    out[0] = make_float4(v[0].x, v[0].y, v[1].x, v[1].y);
    out[1] = make_float4(v[2].x, v[2].y, v[3].x, v[3].y);
}

// ---- Pass 2: forward column FFT (along x), 4 columns per 256-thr block ----
__global__ __launch_bounds__(256) void k_fwd_cols() {
    __shared__ float2 stage[4 * 292];
    __shared__ float2 xch[4][4 * 66];
    int b = blockIdx.x;             // 2*64
    int plane = b >> 6;
    int y0 = (b & 63) * 4;
    float2* base = G_F + plane * NPIX;
    int tid = threadIdx.x;
    for (int i = tid; i < 512; i += 256) {
        int x = i >> 1, h = i & 1;
        float4 ld = *(const float4*)(base + x * 256 + y0 + 2 * h);
        stage[(2 * h) * 292 + x]     = make_float2(ld.x, ld.y);
        stage[(2 * h + 1) * 292 + x] = make_float2(ld.z, ld.w);
    }
    __syncthreads();
    int g = tid >> 6, t = tid & 63;
    float2 v[4];
#pragma unroll
    for (int r = 0; r < 4; r++) v[r] = stage[g * 292 + t + 64 * r];
    group_fft256<false>(v, xch[g], t);
    int k0 = out_k0(t);
#pragma unroll
    for (int q = 0; q < 4; q++) {
        int k = k0 + q;
        stage[g * 292 + k + (k >> 3)] = v[q];
    }
    __syncthreads();
    for (int i = tid; i < 512; i += 256) {
        int x = i >> 1, h = i & 1;
        float2 s0 = stage[(2 * h) * 292 + x + (x >> 3)];
        float2 s1 = stage[(2 * h + 1) * 292 + x + (x >> 3)];
        *(float4*)(base + x * 256 + y0 + 2 * h) = make_float4(s0.x, s0.y, s1.x, s1.y);
    }
}

// ---- Pass 3: spectral multiply + inverse row FFT ----
// One block per x-row (512 threads = 8 groups = 8 j-planes). fK row staged
// coalesced into smem; groups read it conflict-free (stride 15 mod 32).
__global__ __launch_bounds__(512) void k_inv_rows(const float* __restrict__ fKr,
                                                  const float* __restrict__ fKi) {
    __shared__ float sKr[3856];
    __shared__ float sKi[3856];
    __shared__ float2 xch[8][4 * 66];
    int tid = threadIdx.x;
    int x = blockIdx.x;             // 0..255
    // stage fK row x (256 px * 15 k), fully coalesced
    {
        const float* br = fKr + x * 3840;
        const float* bi = fKi + x * 3840;
        for (int i = tid; i < 3840; i += 512) {
            sKr[i] = br[i];
            sKi[i] = bi[i];
        }
    }
    __syncthreads();
    int g = tid >> 6, t = tid & 63;
    int j = g;
    int k1 = 2 * j, k2 = 2 * j + 1;
    bool k2v = (j < 7);
    int c1 = k1 % 3, c2 = k2 % 3;
    int xr = (256 - x) & 255;
    float2 v[4];
#pragma unroll
    for (int r = 0; r < 4; r++) {
        int y = t + 64 * r;
        int gi = x * 256 + y;
        int yr = (256 - y) & 255;
        float2 fv = G_F[gi];
        float2 fr = G_F[xr * 256 + yr];
        float2 fa0 = make_float2(0.5f * (fv.x + fr.x), 0.5f * (fv.y - fr.y));
        float2 fa1 = make_float2(0.5f * (fv.y + fr.y), 0.5f * (fr.x - fv.x));
        float2 fa2 = G_F[NPIX + gi];
        float2 fc1 = (c1 == 0) ? fa0 : ((c1 == 1) ? fa1 : fa2);
        float2 H1 = cmulf(make_float2(sKr[y * 15 + k1], sKi[y * 15 + k1]), fc1);
        float2 H2 = make_float2(0.f, 0.f);
        if (k2v) {
            float2 fc2 = (c2 == 0) ? fa0 : ((c2 == 1) ? fa1 : fa2);
            H2 = cmulf(make_float2(sKr[y * 15 + k2], sKi[y * 15 + k2]), fc2);
        }
        v[r] = make_float2(H1.x - H2.y, H1.y + H2.x);
    }
    group_fft256<true>(v, xch[g], t);
    int k0 = out_k0(t);
    float4* out = (float4*)(G_TMP + j * NPIX + x * 256 + k0);
    out[0] = make_float4(v[0].x, v[0].y, v[1].x, v[1].y);
    out[1] = make_float4(v[2].x, v[2].y, v[3].x, v[3].y);
}

// ---- Pass 4: inverse column FFT + growth -> g_G[k1], g_G[k2] ----
__global__ __launch_bounds__(256) void k_inv_cols(const float* __restrict__ m,
                                                  const float* __restrict__ s) {
    __shared__ float2 stage[4 * 292];
    __shared__ float2 xch[4][4 * 66];
    int b = blockIdx.x;             // 8*64
    int j = b >> 6;
    int y0 = (b & 63) * 4;
    int k1 = 2 * j, k2 = 2 * j + 1;
    bool k2v = (j < 7);
    float2* base = G_TMP + j * NPIX;
    int tid = threadIdx.x;
    for (int i = tid; i < 512; i += 256) {
        int x = i >> 1, h = i & 1;
        float4 ld = *(const float4*)(base + x * 256 + y0 + 2 * h);
        stage[(2 * h) * 292 + x]     = make_float2(ld.x, ld.y);
        stage[(2 * h + 1) * 292 + x] = make_float2(ld.z, ld.w);
    }
    __syncthreads();
    int g = tid >> 6, t = tid & 63;
    float2 v[4];
#pragma unroll
    for (int r = 0; r < 4; r++) v[r] = stage[g * 292 + t + 64 * r];
    group_fft256<true>(v, xch[g], t);
    float m1 = m[k1], s1 = s[k1];
    float i2s1 = 1.0f / (2.0f * s1 * s1);
    float m2 = k2v ? m[k2] : 0.f, s2 = k2v ? s[k2] : 1.f;
    float i2s2 = 1.0f / (2.0f * s2 * s2);
    int k0 = out_k0(t);
#pragma unroll
    for (int q = 0; q < 4; q++) {
        float u1 = v[q].x * (1.0f / 65536.0f);
        float t1 = u1 - m1;
        float g1 = fmaf(2.0f, __expf(-t1 * t1 * i2s1), -1.0f);
        float u2 = v[q].y * (1.0f / 65536.0f);
        float t2 = u2 - m2;
        float g2 = fmaf(2.0f, __expf(-t2 * t2 * i2s2), -1.0f);
        int k = k0 + q;
        stage[g * 292 + k + (k >> 3)] = make_float2(g1, g2);
    }
    __syncthreads();
    for (int i = tid; i < 512; i += 256) {
        int x = i & 255, pl = i >> 8;
        if (pl == 1 && !k2v) continue;
        float2 s0 = stage[0 * 292 + x + (x >> 3)];
        float2 s1 = stage[1 * 292 + x + (x >> 3)];
        float2 s2 = stage[2 * 292 + x + (x >> 3)];
        float2 s3 = stage[3 * 292 + x + (x >> 3)];
        float4 out = (pl == 0) ? make_float4(s0.x, s1.x, s2.x, s3.x)
                               : make_float4(s0.y, s1.y, s2.y, s3.y);
        int kk = (pl == 0) ? k1 : k2;
        *(float4*)(g_G + kk * NPIX + x * 256 + y0) = out;
    }
}

// ---- Pass 5: fused UcAs (18x18 halo tile) + Sobel + mu ----
__global__ __launch_bounds__(256) void k_ucas_sobel(const float* __restrict__ A,
                                                    const float* __restrict__ P) {
    const float SIGMA = 0.65f, MAB = 4.35f, DT = 0.2f;
    __shared__ float4 sU[18 * 18];
    int x0 = blockIdx.y * 16;
    int y0 = blockIdx.x * 16;
    int tid = threadIdx.x;
    for (int i = tid; i < 324; i += 256) {
        int ti = i / 18, tj = i - ti * 18;
        int gx = x0 + ti - 1, gy = y0 + tj - 1;
        float4 val = make_float4(0.f, 0.f, 0.f, 0.f);
        if ((unsigned)gx < 256u && (unsigned)gy < 256u) {
            int gi = gx * 256 + gy;
            float u[3] = {0.f, 0.f, 0.f};
#pragma unroll
            for (int k = 0; k < 15; k++) u[k % 3] += g_G[k * NPIX + gi] * P[gi * 15 + k];
            val = make_float4(u[0], u[1], u[2],
                              A[gi * 3 + 0] + A[gi * 3 + 1] + A[gi * 3 + 2]);
        }
        sU[i] = val;
    }
    __syncthreads();
    int li = tid >> 4, lj = tid & 15;
    int x = x0 + li, y = y0 + lj;
    int i = x * 256 + y;
    float4 S[3][3];
#pragma unroll
    for (int du = 0; du < 3; du++)
#pragma unroll
        for (int dv = 0; dv < 3; dv++)
            S[du][dv] = sU[(li + du) * 18 + (lj + dv)];
    float gy[4], gx[4];
    {
        float4 b0 = S[2][0], b1 = S[2][1], b2 = S[2][2];
        float4 t0 = S[0][0], t1 = S[0][1], t2 = S[0][2];
        gy[0] = (b0.x + 2.f * b1.x + b2.x) - (t0.x + 2.f * t1.x + t2.x);
        gy[1] = (b0.y + 2.f * b1.y + b2.y) - (t0.y + 2.f * t1.y + t2.y);
        gy[2] = (b0.z + 2.f * b1.z + b2.z) - (t0.z + 2.f * t1.z + t2.z);
        gy[3] = (b0.w + 2.f * b1.w + b2.w) - (t0.w + 2.f * t1.w + t2.w);
        float4 r0 = S[0][2], r1 = S[1][2], r2 = S[2][2];
        float4 l0 = S[0][0], l1 = S[1][0], l2 = S[2][0];
        gx[0] = (r0.x + 2.f * r1.x + r2.x) - (l0.x + 2.f * l1.x + l2.x);
        gx[1] = (r0.y + 2.f * r1.y + r2.y) - (l0.y + 2.f * l1.y + l2.y);
        gx[2] = (r0.z + 2.f * r1.z + r2.z) - (l0.z + 2.f * l1.z + l2.z);
        gx[3] = (r0.w + 2.f * r1.w + r2.w) - (l0.w + 2.f * l1.w + l2.w);
    }
    float pr = (float)x + 0.5f, pc = (float)y + 0.5f;
#pragma unroll
    for (int c = 0; c < 3; c++) {
        float a = A[i * 3 + c];
        float al = fminf(0.25f * a * a, 1.0f);
        float Fy = gy[c] * (1.0f - al) - gy[3] * al;
        float Fx = gx[c] * (1.0f - al) - gx[3] * al;
        Fy = fminf(fmaxf(Fy, -MAB), MAB);
        Fx = fminf(fmaxf(Fx, -MAB), MAB);
        float mur = fminf(fmaxf(pr + DT * Fy, SIGMA), 256.0f - SIGMA);
        float muc = fminf(fmaxf(pc + DT * Fx, SIGMA), 256.0f - SIGMA);
        g_mu[i * 6 + c]     = mur;
        g_mu[i * 6 + 3 + c] = muc;
    }
}

// ---- Pass 6: reintegration gather (25-source window), softmax-mixed P ----
__global__ __launch_bounds__(256) void k_reint(const float* __restrict__ A,
                                               const float* __restrict__ P,
                                               float* __restrict__ outA,
                                               float* __restrict__ outP) {
    const float SIGMA = 0.65f;
    const float INV4S2 = 1.0f / (4.0f * 0.65f * 0.65f);
    __shared__ float s_mu[400 * 6];
    __shared__ float s_A[400 * 3];
    __shared__ __align__(16) float s_P[400 * 20];
    int x0 = blockIdx.y * 16;
    int y0 = blockIdx.x * 16;
    int tid = threadIdx.x;
    for (int cidx = tid; cidx < 400; cidx += 256) {
        int ti = cidx / 20, tj = cidx - ti * 20;
        int gx = x0 + ti - 2, gy = y0 + tj - 2;
        bool ok = (unsigned)gx < 256u && (unsigned)gy < 256u;
        int gi = gx * 256 + gy;
#pragma unroll
        for (int f = 0; f < 6; f++) s_mu[cidx * 6 + f] = ok ? g_mu[gi * 6 + f] : -1.0e4f;
#pragma unroll
        for (int c = 0; c < 3; c++) s_A[cidx * 3 + c] = ok ? A[gi * 3 + c] : 0.0f;
#pragma unroll
        for (int k = 0; k < 15; k++) s_P[cidx * 20 + k] = ok ? P[gi * 15 + k] : 0.0f;
        s_P[cidx * 20 + 15] = 0.0f;
    }
    __syncthreads();

    int li = tid >> 4, lj = tid & 15;
    int x = x0 + li, y = y0 + lj;
    float pr = (float)x + 0.5f, pc = (float)y + 0.5f;
    float accA[3] = {0.f, 0.f, 0.f};
    float4 n0 = make_float4(0.f, 0.f, 0.f, 0.f), n1 = n0, n2 = n0, n3 = n0;
    float den = 0.0f;

    for (int di = 0; di < 5; di++) {
#pragma unroll
        for (int dj = 0; dj < 5; dj++) {
            int cell = (li + di) * 20 + (lj + dj);
            const float* mu = &s_mu[cell * 6];
            float ssum = 0.0f;
#pragma unroll
            for (int c = 0; c < 3; c++) {
                float szr = 0.5f + SIGMA - fabsf(pr - mu[c]);
                float szc = 0.5f + SIGMA - fabsf(pc - mu[3 + c]);
                float ar = fminf(fmaxf(szr, 0.0f), 1.0f) *
                           fminf(fmaxf(szc, 0.0f), 1.0f) * INV4S2;
                float nA = s_A[cell * 3 + c] * ar;
                accA[c] += nA;
                ssum += nA;
            }
            // ssum >= 0; ssum == 0 -> e == 0 -> exactly zero contribution
            if (ssum != 0.0f) {
                float e = __expf(ssum) - 1.0f;
                den += e;
                const float4* p4 = (const float4*)(s_P + cell * 20);
                float4 a0 = p4[0], a1 = p4[1], a2 = p4[2], a3 = p4[3];
                n0.x += a0.x * e; n0.y += a0.y * e; n0.z += a0.z * e; n0.w += a0.w * e;
                n1.x += a1.x * e; n1.y += a1.y * e; n1.z += a1.z * e; n1.w += a1.w * e;
                n2.x += a2.x * e; n2.y += a2.y * e; n2.z += a2.z * e; n2.w += a2.w * e;
                n3.x += a3.x * e; n3.y += a3.y * e; n3.z += a3.z * e;
            }
        }
    }
    int gi = x * 256 + y;
#pragma unroll
    for (int c = 0; c < 3; c++) outA[gi * 3 + c] = accA[c];
    float inv = 1.0f / (den + 1e-10f);
    float num[15] = {n0.x, n0.y, n0.z, n0.w, n1.x, n1.y, n1.z, n1.w,
                     n2.x, n2.y, n2.z, n2.w, n3.x, n3.y, n3.z};
#pragma unroll
    for (int k = 0; k < 15; k++) outP[gi * 15 + k] = num[k] * inv;
}

extern "C" void kernel_launch(void* const* d_in, const int* in_sizes, int n_in,
                              void* d_out, int out_size) {
    const float* A   = (const float*)d_in[0];
    const float* P   = (const float*)d_in[1];
    const float* fKr = (const float*)d_in[2];
    const float* fKi = (const float*)d_in[3];
    const float* m   = (const float*)d_in[4];
    const float* s   = (const float*)d_in[5];
    float* outA = (float*)d_out;
    float* outP = (float*)d_out + 256 * 256 * 3;

    k_fwd_rows<<<128, 256>>>(A);
    k_fwd_cols<<<128, 256>>>();
    k_inv_rows<<<256, 512>>>(fKr, fKi);
    k_inv_cols<<<512, 256>>>(m, s);
    k_ucas_sobel<<<dim3(16, 16), 256>>>(A, P);
    k_reint<<<dim3(16, 16), 256>>>(A, P, outA, outP);
}